// round 13
// baseline (speedup 1.0000x reference)
#include <cuda_runtime.h>
#include <cstdint>

typedef unsigned long long ull;

#define B_      2
#define L_      4096
#define HIDDEN  512
#define HEADS   8
#define HD      64
#define PREFIX  1
#define M_ROWS  (B_ * L_)        // 8192

// ---- fp16 storage (allocation-free: __device__ globals) ----
__device__ __align__(16) uint16_t gx_f16[M_ROWS * HIDDEN];
__device__ __align__(16) uint16_t gwi_f16[3 * HIDDEN * HIDDEN];
__device__ __align__(16) uint16_t gwo_f16[HIDDEN * HIDDEN];
__device__ __align__(16) uint16_t gq_f16[M_ROWS * HIDDEN];
__device__ __align__(16) uint16_t gk_f16[M_ROWS * HIDDEN];
__device__ __align__(16) uint16_t gv_f16[M_ROWS * HIDDEN];
__device__ __align__(16) uint16_t gctx_f16[M_ROWS * HIDDEN];

// ============================================================
// helpers
// ============================================================
__device__ __forceinline__ uint32_t smem_u32(const void* p) {
    uint32_t a;
    asm("{ .reg .u64 t; cvta.to.shared.u64 t, %1; cvt.u32.u64 %0, t; }" : "=r"(a) : "l"(p));
    return a;
}
__device__ __forceinline__ uint32_t cvt_f16x2(float lo, float hi) {
    uint32_t r; asm("cvt.rn.f16x2.f32 %0,%1,%2;" : "=r"(r) : "f"(hi), "f"(lo)); return r;
}
__device__ __forceinline__ float ex2f(float x) {
    float r; asm("ex2.approx.f32 %0,%1;" : "=f"(r) : "f"(x)); return r;
}
__device__ __forceinline__ uint32_t swz128(uint32_t o) { return o ^ ((o >> 3) & 0x70u); }
__device__ __forceinline__ uint32_t swz64(uint32_t o)  { return o ^ ((o >> 3) & 0x30u); }

__device__ __forceinline__ void cp16(uint32_t dst, const void* src) {
    asm volatile("cp.async.cg.shared.global [%0], [%1], 16;" :: "r"(dst), "l"(src) : "memory");
}
__device__ __forceinline__ void cp_commit() {
    asm volatile("cp.async.commit_group;" ::: "memory");
}
template <int N> __device__ __forceinline__ void cp_wait() {
    asm volatile("cp.async.wait_group %0;" :: "n"(N) : "memory");
}

__device__ __forceinline__ void ldsm4(uint32_t& r0, uint32_t& r1, uint32_t& r2, uint32_t& r3,
                                      uint32_t addr) {
    asm volatile("ldmatrix.sync.aligned.m8n8.x4.shared.b16 {%0,%1,%2,%3}, [%4];"
                 : "=r"(r0), "=r"(r1), "=r"(r2), "=r"(r3) : "r"(addr));
}
__device__ __forceinline__ void ldsm4t(uint32_t& r0, uint32_t& r1, uint32_t& r2, uint32_t& r3,
                                       uint32_t addr) {
    asm volatile("ldmatrix.sync.aligned.m8n8.x4.trans.shared.b16 {%0,%1,%2,%3}, [%4];"
                 : "=r"(r0), "=r"(r1), "=r"(r2), "=r"(r3) : "r"(addr));
}
__device__ __forceinline__ void mma_f16(float* c, const uint32_t* a, uint32_t b0, uint32_t b1) {
    asm volatile(
        "mma.sync.aligned.m16n8k16.row.col.f32.f16.f16.f32 "
        "{%0,%1,%2,%3},{%4,%5,%6,%7},{%8,%9},{%0,%1,%2,%3};"
        : "+f"(c[0]), "+f"(c[1]), "+f"(c[2]), "+f"(c[3])
        : "r"(a[0]), "r"(a[1]), "r"(a[2]), "r"(a[3]), "r"(b0), "r"(b1));
}

// ============================================================
// conversion kernels: fp32 -> fp16
// ============================================================
__global__ __launch_bounds__(256) void conv_x_kernel(const float* __restrict__ x)
{
    size_t gid = (size_t)blockIdx.x * 256 + threadIdx.x;
    size_t i = gid * 4;
    float4 v = *(const float4*)(x + i);
    uint2 H;
    H.x = cvt_f16x2(v.x, v.y);
    H.y = cvt_f16x2(v.z, v.w);
    *(uint2*)(gx_f16 + i) = H;
}

__global__ __launch_bounds__(256) void conv_wT_kernel(const float* __restrict__ w,
                                                      int K, int N, int which)
{
    __shared__ float t[32][33];
    uint16_t* dst = which ? gwo_f16 : gwi_f16;
    int n0 = blockIdx.x * 32, k0 = blockIdx.y * 32;
    int tx = threadIdx.x & 31, ty = threadIdx.x >> 5;
#pragma unroll
    for (int i = 0; i < 4; i++)
        t[ty + 8 * i][tx] = w[(size_t)(k0 + ty + 8 * i) * N + n0 + tx];
    __syncthreads();
#pragma unroll
    for (int i = 0; i < 4; i++) {
        int nn = ty + 8 * i;
        float v = t[tx][nn];
        uint16_t h;
        asm("cvt.rn.f16.f32 %0,%1;" : "=h"(h) : "f"(v));
        dst[(size_t)(n0 + nn) * K + k0 + tx] = h;
    }
}

// ============================================================
// GEMM fp16: CTA tile 256x128, 256 thr, warp tile 64x64 (4x2),
// k-chunk 32, 3-stage cp.async, SW64. 1 CTA/SM.
// Stage (24KB): {A 0 (16KB), B 16384 (8KB)}.
// ============================================================
#define GSTAGE 24576u

template <int MODE>
__global__ __launch_bounds__(256, 1) void gemm_f16_kernel(
    const float* __restrict__ bias, float* __restrict__ Cout)
{
    extern __shared__ char smp[];
    const uint32_t sbase = smem_u32(smp);
    int tid = threadIdx.x;
    int lane = tid & 31, w = tid >> 5;
    int wm = w >> 1, wn = w & 1;     // 4 x 2 warp grid, warp tile 64x64
    int bm = blockIdx.y, bn = blockIdx.x;

    const uint16_t* A = (MODE == 0) ? gx_f16 : gctx_f16;
    const uint16_t* Bw = (MODE == 0) ? gwi_f16 : gwo_f16;

    // A loader: 1 thr/row (64B), 4 groups. B loader: 2 thr/row, 2 groups.
    int rbr = tid >> 1, gb0 = (tid & 1) * 2;
    size_t aoff = (size_t)(bm * 256 + tid) * HIDDEN;
    size_t boff = (size_t)(bn * 128 + rbr) * HIDDEN;

    float acc[4][8][4];
#pragma unroll
    for (int i = 0; i < 4; i++)
#pragma unroll
        for (int j = 0; j < 8; j++)
#pragma unroll
            for (int e = 0; e < 4; e++) acc[i][j][e] = 0.f;

#define ISSUE_CHUNK(kc, buf) do {                                               \
        uint32_t dst = sbase + (uint32_t)(buf) * GSTAGE;                         \
        const uint16_t* ap = A  + aoff + (kc) * 32;                              \
        const uint16_t* bp = Bw + boff + (kc) * 32;                              \
        _Pragma("unroll")                                                        \
        for (int i = 0; i < 4; i++) {                                            \
            uint32_t so = swz64((uint32_t)tid * 64u + (uint32_t)i * 16u);        \
            cp16(dst + so, ap + i * 8);                                          \
        }                                                                        \
        _Pragma("unroll")                                                        \
        for (int i = 0; i < 2; i++) {                                            \
            uint32_t so = swz64((uint32_t)rbr * 64u + (uint32_t)(gb0 + i) * 16u);\
            cp16(dst + 16384u + so, bp + (gb0 + i) * 8);                         \
        }                                                                        \
        cp_commit();                                                             \
    } while (0)

    ISSUE_CHUNK(0, 0);
    ISSUE_CHUNK(1, 1);

    const int NK = HIDDEN / 32;   // 16 chunks
    int rb = 0;
    for (int kc = 0; kc < NK; kc++) {
        if (kc + 2 < NK) {
            int wb = rb + 2; if (wb >= 3) wb -= 3;
            ISSUE_CHUNK(kc + 2, wb);
            cp_wait<2>();
        } else if (kc + 1 < NK) {
            cp_wait<1>();
        } else {
            cp_wait<0>();
        }
        __syncthreads();

        uint32_t abase = sbase + (uint32_t)rb * GSTAGE;
        uint32_t bbase = abase + 16384u;
#pragma unroll
        for (int ks = 0; ks < 2; ks++) {
            uint32_t ah[4][4];
#pragma unroll
            for (int mi = 0; mi < 4; mi++) {
                uint32_t off = swz64((uint32_t)(wm * 64 + mi * 16 + (lane & 15)) * 64u
                                     + (uint32_t)(ks * 32 + ((lane & 16) ? 16 : 0)));
                ldsm4(ah[mi][0], ah[mi][1], ah[mi][2], ah[mi][3], abase + off);
            }
#pragma unroll
            for (int np = 0; np < 4; np++) {
                uint32_t boffs = swz64((uint32_t)(wn * 64 + np * 16 + (lane & 7)
                                                  + ((lane & 16) ? 8 : 0)) * 64u
                                       + (uint32_t)(ks * 32 + ((lane & 8) ? 16 : 0)));
                uint32_t b0, b1, b2, b3;
                ldsm4(b0, b1, b2, b3, bbase + boffs);
#pragma unroll
                for (int mi = 0; mi < 4; mi++) {
                    mma_f16(acc[mi][2 * np],     ah[mi], b0, b1);
                    mma_f16(acc[mi][2 * np + 1], ah[mi], b2, b3);
                }
            }
        }
        __syncthreads();
        rb = rb + 1; if (rb == 3) rb = 0;
    }
#undef ISSUE_CHUNK

    // ---- epilogue ----
#pragma unroll
    for (int mi = 0; mi < 4; mi++) {
        int r0 = bm * 256 + wm * 64 + mi * 16 + (lane >> 2);
#pragma unroll
        for (int nj = 0; nj < 8; nj++) {
            int c0 = bn * 128 + wn * 64 + nj * 8 + 2 * (lane & 3);
            float bb0 = __ldg(bias + c0), bb1 = __ldg(bias + c0 + 1);
            float v0 = acc[mi][nj][0] + bb0, v1 = acc[mi][nj][1] + bb1;
            float v2 = acc[mi][nj][2] + bb0, v3 = acc[mi][nj][3] + bb1;
            if (MODE == 0) {
                int which = c0 >> 9, h = (c0 >> 6) & 7, d = c0 & 63;
                uint16_t* dq = (which == 0) ? gq_f16 : (which == 1) ? gk_f16 : gv_f16;
                int b = r0 >> 12;
                size_t base0 = ((size_t)((b * 8 + h) * L_ + (r0 & 4095))) * 64 + d;
                size_t base1 = base0 + 8 * 64;
                *(uint32_t*)(dq + base0) = cvt_f16x2(v0, v1);
                *(uint32_t*)(dq + base1) = cvt_f16x2(v2, v3);
            } else {
                *(float2*)(Cout + (size_t)r0 * HIDDEN + c0) = make_float2(v0, v1);
                *(float2*)(Cout + (size_t)(r0 + 8) * HIDDEN + c0) = make_float2(v2, v3);
            }
        }
    }
}

// ============================================================
// Attention fp16: q-tile 256 rows, 8 warps x 32 rows, 32-key tiles.
// SMEM: Q 32KB; K/V double buffer 2 x 8KB (K 4KB + V 4KB). 48KB.
// 1 CTA/SM.
// ============================================================
#define SQ   0u
#define SKV0 32768u
#define ATTN_SMEM 49152

__global__ __launch_bounds__(256, 1) void attn_mma_kernel()
{
    extern __shared__ char smp[];
    const uint32_t sbase = smem_u32(smp);
    int tid = threadIdx.x;
    int w = tid >> 5, lane = tid & 31;

    int bh = blockIdx.x;                            // b*8 + h
    int qt = (int)gridDim.y - 1 - (int)blockIdx.y;  // heavy tiles first
    int nkt = 8 * qt + 8;                           // 32-key tiles

    // K/V loaders: 128 threads each; 4 thr/row, 2 cp16 per thread
    int ct = tid & 127;
    int rr = ct >> 2, g0 = (ct & 3) * 2;
    const uint16_t* srckv = (tid < 128) ? gk_f16 : gv_f16;
    uint32_t dsel = (tid < 128) ? 0u : 4096u;

#define ISSUE_KV(kt, buf) do {                                                   \
        uint32_t dst = sbase + SKV0 + (uint32_t)(buf) * 8192u + dsel;            \
        const uint16_t* sp = srckv + ((size_t)bh * L_ + (size_t)(kt) * 32 + rr) * 64; \
        _Pragma("unroll")                                                        \
        for (int i = 0; i < 2; i++) {                                            \
            uint32_t so = swz128((uint32_t)rr * 128u + (uint32_t)(g0 + i) * 16u);\
            cp16(dst + so, sp + (g0 + i) * 8);                                   \
        }                                                                        \
        cp_commit();                                                             \
    } while (0)

    // Prologue: Q tile copy (256 rows, 1 thr/row) + first K/V issue
    {
        const uint4* q4 = (const uint4*)(gq_f16 + ((size_t)bh * L_ + (size_t)qt * 256 + tid) * 64);
#pragma unroll
        for (int i = 0; i < 8; i++) {
            uint32_t so = swz128((uint32_t)tid * 128u + (uint32_t)i * 16u);
            *(uint4*)(smp + SQ + so) = q4[i];
        }
    }
    ISSUE_KV(0, 0);
    __syncthreads();

    // Q fragments: 32 rows/warp = 2 A-frags per ks
    uint32_t qf[4][2][4];
    {
#pragma unroll
        for (int ks = 0; ks < 4; ks++)
#pragma unroll
            for (int mi = 0; mi < 2; mi++) {
                uint32_t off = swz128((uint32_t)(32 * w + 16 * mi + (lane & 15)) * 128u
                                      + (uint32_t)(ks * 32 + ((lane & 16) ? 16 : 0)));
                ldsm4(qf[ks][mi][0], qf[ks][mi][1], qf[ks][mi][2], qf[ks][mi][3],
                      sbase + SQ + off);
            }
    }

    float oc[2][8][4];
#pragma unroll
    for (int mi = 0; mi < 2; mi++)
#pragma unroll
        for (int n = 0; n < 8; n++)
#pragma unroll
            for (int j = 0; j < 4; j++) oc[mi][n][j] = 0.f;
    float ls[2][2] = {{0.f, 0.f}, {0.f, 0.f}};

    const float Cc = 0.18033688011112042f;  // (1/8) * log2(e)
    int rbase = qt * 256 + 32 * w + (lane >> 2);

    for (int kt = 0; kt < nkt; ++kt) {
        if (kt + 1 < nkt) {
            ISSUE_KV(kt + 1, (kt + 1) & 1);
            cp_wait<1>();
        } else {
            cp_wait<0>();
        }
        __syncthreads();

        uint32_t kvb = sbase + SKV0 + (uint32_t)(kt & 1) * 8192u;

        // ---- S = Q K^T : M32 x N32 per warp ----
        float sc[2][4][4];
#pragma unroll
        for (int mi = 0; mi < 2; mi++)
#pragma unroll
            for (int n = 0; n < 4; n++)
#pragma unroll
                for (int j = 0; j < 4; j++) sc[mi][n][j] = 0.f;

#pragma unroll
        for (int ks = 0; ks < 4; ks++) {
#pragma unroll
            for (int npp = 0; npp < 2; npp++) {
                int key = npp * 16 + (lane & 7) + ((lane & 16) ? 8 : 0);
                uint32_t off = swz128((uint32_t)key * 128u
                                      + (uint32_t)(ks * 32 + ((lane & 8) ? 16 : 0)));
                uint32_t b0, b1, b2, b3;
                ldsm4(b0, b1, b2, b3, kvb + off);
#pragma unroll
                for (int mi = 0; mi < 2; mi++) {
                    mma_f16(sc[mi][2 * npp],     qf[ks][mi], b0, b1);
                    mma_f16(sc[mi][2 * npp + 1], qf[ks][mi], b2, b3);
                }
            }
        }

        // ---- softmax (unnormalized) ----
        bool edge = (kt == 0) || (kt * 32 + 31 > qt * 256 + 32 * w);
        int colb = kt * 32 + 2 * (lane & 3);
#pragma unroll
        for (int mi = 0; mi < 2; mi++) {
            int r0 = rbase + 16 * mi, r1 = r0 + 8;
#pragma unroll
            for (int n = 0; n < 4; n++) {
                float e0 = ex2f(sc[mi][n][0] * Cc);
                float e1 = ex2f(sc[mi][n][1] * Cc);
                float e2 = ex2f(sc[mi][n][2] * Cc);
                float e3 = ex2f(sc[mi][n][3] * Cc);
                if (edge) {
                    int c0 = colb + 8 * n, c1 = c0 + 1;
                    bool k00 = (c0 <= r0) && (c0 >= PREFIX || r0 < PREFIX);
                    bool k01 = (c1 <= r0) && (c1 >= PREFIX || r0 < PREFIX);
                    bool k10 = (c0 <= r1) && (c0 >= PREFIX || r1 < PREFIX);
                    bool k11 = (c1 <= r1) && (c1 >= PREFIX || r1 < PREFIX);
                    e0 = k00 ? e0 : 0.f;
                    e1 = k01 ? e1 : 0.f;
                    e2 = k10 ? e2 : 0.f;
                    e3 = k11 ? e3 : 0.f;
                }
                sc[mi][n][0] = e0; sc[mi][n][1] = e1;
                sc[mi][n][2] = e2; sc[mi][n][3] = e3;
                ls[mi][0] += e0 + e1;
                ls[mi][1] += e2 + e3;
            }
        }

        // ---- O += P V : V frags shared across mi ----
#pragma unroll
        for (int t = 0; t < 2; t++) {
            uint32_t pf[2][4];
#pragma unroll
            for (int mi = 0; mi < 2; mi++) {
                pf[mi][0] = cvt_f16x2(sc[mi][2 * t][0],     sc[mi][2 * t][1]);
                pf[mi][1] = cvt_f16x2(sc[mi][2 * t][2],     sc[mi][2 * t][3]);
                pf[mi][2] = cvt_f16x2(sc[mi][2 * t + 1][0], sc[mi][2 * t + 1][1]);
                pf[mi][3] = cvt_f16x2(sc[mi][2 * t + 1][2], sc[mi][2 * t + 1][3]);
            }
            int key = t * 16 + (lane & 7) + ((lane & 8) ? 8 : 0);
#pragma unroll
            for (int dpp = 0; dpp < 2; dpp++) {
                uint32_t col0 = (uint32_t)((2 * dpp) * 32 + ((lane & 16) ? 16 : 0));
                uint32_t off0 = swz128((uint32_t)key * 128u + col0);
                uint32_t off1 = swz128((uint32_t)key * 128u + col0 + 32u);
                uint32_t v00, v01, v02, v03, v10, v11, v12, v13;
                ldsm4t(v00, v01, v02, v03, kvb + 4096u + off0);
                ldsm4t(v10, v11, v12, v13, kvb + 4096u + off1);
#pragma unroll
                for (int mi = 0; mi < 2; mi++) {
                    mma_f16(oc[mi][4 * dpp + 0], pf[mi], v00, v01);
                    mma_f16(oc[mi][4 * dpp + 1], pf[mi], v02, v03);
                    mma_f16(oc[mi][4 * dpp + 2], pf[mi], v10, v11);
                    mma_f16(oc[mi][4 * dpp + 3], pf[mi], v12, v13);
                }
            }
        }
        __syncthreads();
    }
#undef ISSUE_KV

    // lane reduction of lsum (rows live in lanes sharing lane>>2)
#pragma unroll
    for (int mi = 0; mi < 2; mi++) {
#pragma unroll
        for (int s = 0; s < 2; s++) {
            ls[mi][s] += __shfl_xor_sync(0xffffffffu, ls[mi][s], 1);
            ls[mi][s] += __shfl_xor_sync(0xffffffffu, ls[mi][s], 2);
        }
    }

    // store ctx as fp16
    int b = bh >> 3, h = bh & 7;
#pragma unroll
    for (int mi = 0; mi < 2; mi++) {
        float inv0 = 1.f / ls[mi][0], inv1 = 1.f / ls[mi][1];
        int r0 = rbase + 16 * mi;
        size_t r0base = (size_t)(b * L_ + r0) * HIDDEN + h * 64;
        size_t r1base = (size_t)(b * L_ + r0 + 8) * HIDDEN + h * 64;
#pragma unroll
        for (int n = 0; n < 8; n++) {
            int d = 8 * n + 2 * (lane & 3);
            *(uint32_t*)(gctx_f16 + r0base + d) =
                cvt_f16x2(oc[mi][n][0] * inv0, oc[mi][n][1] * inv0);
            *(uint32_t*)(gctx_f16 + r1base + d) =
                cvt_f16x2(oc[mi][n][2] * inv1, oc[mi][n][3] * inv1);
        }
    }
}

// ============================================================
extern "C" void kernel_launch(void* const* d_in, const int* in_sizes, int n_in,
                              void* d_out, int out_size)
{
    const float* x     = (const float*)d_in[0];
    const float* w_in  = (const float*)d_in[1];
    const float* b_in  = (const float*)d_in[2];
    const float* w_out = (const float*)d_in[3];
    const float* b_out = (const float*)d_in[4];
    float* out = (float*)d_out;

    conv_x_kernel<<<(M_ROWS * HIDDEN / 4) / 256, 256>>>(x);
    conv_wT_kernel<<<dim3(3 * HIDDEN / 32, HIDDEN / 32), 256>>>(w_in, HIDDEN, 3 * HIDDEN, 0);
    conv_wT_kernel<<<dim3(HIDDEN / 32, HIDDEN / 32), 256>>>(w_out, HIDDEN, HIDDEN, 1);

    cudaFuncSetAttribute(gemm_f16_kernel<0>,
                         cudaFuncAttributeMaxDynamicSharedMemorySize, 3 * GSTAGE);
    gemm_f16_kernel<0><<<dim3(12, 32), 256, 3 * GSTAGE>>>(b_in, nullptr);

    cudaFuncSetAttribute(attn_mma_kernel,
                         cudaFuncAttributeMaxDynamicSharedMemorySize, ATTN_SMEM);
    attn_mma_kernel<<<dim3(16, 16), 256, ATTN_SMEM>>>();

    cudaFuncSetAttribute(gemm_f16_kernel<1>,
                         cudaFuncAttributeMaxDynamicSharedMemorySize, 3 * GSTAGE);
    gemm_f16_kernel<1><<<dim3(4, 32), 256, 3 * GSTAGE>>>(b_out, out);
}

// round 14
// speedup vs baseline: 1.1898x; 1.1898x over previous
#include <cuda_runtime.h>
#include <cstdint>

typedef unsigned long long ull;

#define B_      2
#define L_      4096
#define HIDDEN  512
#define HEADS   8
#define HD      64
#define PREFIX  1
#define M_ROWS  (B_ * L_)        // 8192

// ---- fp16 storage (allocation-free: __device__ globals) ----
__device__ __align__(16) uint16_t gx_f16[M_ROWS * HIDDEN];
__device__ __align__(16) uint16_t gwi_f16[3 * HIDDEN * HIDDEN];
__device__ __align__(16) uint16_t gwo_f16[HIDDEN * HIDDEN];
__device__ __align__(16) uint16_t gq_f16[M_ROWS * HIDDEN];
__device__ __align__(16) uint16_t gk_f16[M_ROWS * HIDDEN];
__device__ __align__(16) uint16_t gv_f16[M_ROWS * HIDDEN];
__device__ __align__(16) uint16_t gctx_f16[M_ROWS * HIDDEN];

// ============================================================
// helpers
// ============================================================
__device__ __forceinline__ uint32_t smem_u32(const void* p) {
    uint32_t a;
    asm("{ .reg .u64 t; cvta.to.shared.u64 t, %1; cvt.u32.u64 %0, t; }" : "=r"(a) : "l"(p));
    return a;
}
__device__ __forceinline__ uint32_t cvt_f16x2(float lo, float hi) {
    uint32_t r; asm("cvt.rn.f16x2.f32 %0,%1,%2;" : "=r"(r) : "f"(hi), "f"(lo)); return r;
}
__device__ __forceinline__ float ex2f(float x) {
    float r; asm("ex2.approx.f32 %0,%1;" : "=f"(r) : "f"(x)); return r;
}
__device__ __forceinline__ uint32_t swz128(uint32_t o) { return o ^ ((o >> 3) & 0x70u); }
__device__ __forceinline__ uint32_t swz64(uint32_t o)  { return o ^ ((o >> 3) & 0x30u); }

__device__ __forceinline__ void cp16(uint32_t dst, const void* src) {
    asm volatile("cp.async.cg.shared.global [%0], [%1], 16;" :: "r"(dst), "l"(src) : "memory");
}
__device__ __forceinline__ void cp_commit() {
    asm volatile("cp.async.commit_group;" ::: "memory");
}
template <int N> __device__ __forceinline__ void cp_wait() {
    asm volatile("cp.async.wait_group %0;" :: "n"(N) : "memory");
}

__device__ __forceinline__ void ldsm4(uint32_t& r0, uint32_t& r1, uint32_t& r2, uint32_t& r3,
                                      uint32_t addr) {
    asm volatile("ldmatrix.sync.aligned.m8n8.x4.shared.b16 {%0,%1,%2,%3}, [%4];"
                 : "=r"(r0), "=r"(r1), "=r"(r2), "=r"(r3) : "r"(addr));
}
__device__ __forceinline__ void ldsm4t(uint32_t& r0, uint32_t& r1, uint32_t& r2, uint32_t& r3,
                                       uint32_t addr) {
    asm volatile("ldmatrix.sync.aligned.m8n8.x4.trans.shared.b16 {%0,%1,%2,%3}, [%4];"
                 : "=r"(r0), "=r"(r1), "=r"(r2), "=r"(r3) : "r"(addr));
}
__device__ __forceinline__ void mma_f16(float* c, const uint32_t* a, uint32_t b0, uint32_t b1) {
    asm volatile(
        "mma.sync.aligned.m16n8k16.row.col.f32.f16.f16.f32 "
        "{%0,%1,%2,%3},{%4,%5,%6,%7},{%8,%9},{%0,%1,%2,%3};"
        : "+f"(c[0]), "+f"(c[1]), "+f"(c[2]), "+f"(c[3])
        : "r"(a[0]), "r"(a[1]), "r"(a[2]), "r"(a[3]), "r"(b0), "r"(b1));
}

// ============================================================
// conversion kernels: fp32 -> fp16
// ============================================================
__global__ __launch_bounds__(256) void conv_x_kernel(const float* __restrict__ x)
{
    size_t gid = (size_t)blockIdx.x * 256 + threadIdx.x;
    size_t i = gid * 4;
    float4 v = *(const float4*)(x + i);
    uint2 H;
    H.x = cvt_f16x2(v.x, v.y);
    H.y = cvt_f16x2(v.z, v.w);
    *(uint2*)(gx_f16 + i) = H;
}

__global__ __launch_bounds__(256) void conv_wT_kernel(const float* __restrict__ w,
                                                      int K, int N, int which)
{
    __shared__ float t[32][33];
    uint16_t* dst = which ? gwo_f16 : gwi_f16;
    int n0 = blockIdx.x * 32, k0 = blockIdx.y * 32;
    int tx = threadIdx.x & 31, ty = threadIdx.x >> 5;
#pragma unroll
    for (int i = 0; i < 4; i++)
        t[ty + 8 * i][tx] = w[(size_t)(k0 + ty + 8 * i) * N + n0 + tx];
    __syncthreads();
#pragma unroll
    for (int i = 0; i < 4; i++) {
        int nn = ty + 8 * i;
        float v = t[tx][nn];
        uint16_t h;
        asm("cvt.rn.f16.f32 %0,%1;" : "=h"(h) : "f"(v));
        dst[(size_t)(n0 + nn) * K + k0 + tx] = h;
    }
}

// ============================================================
// GEMM single-pass fp16: CTA tile 128x128, 256 thr, warp tile 32x64,
// k-chunk 32, 3-stage ring + depth-1 prefetch, ONE sync per chunk,
// SW64, 2 CTA/SM. Stage (16KB): {A 0, B 8K}.
// ============================================================
#define GSTAGE 16384u

template <int MODE>
__global__ __launch_bounds__(256, 2) void gemm_f16_kernel(
    const float* __restrict__ bias, float* __restrict__ Cout)
{
    extern __shared__ char smp[];
    const uint32_t sbase = smem_u32(smp);
    int tid = threadIdx.x;
    int lane = tid & 31, w = tid >> 5;
    int wm = w >> 1, wn = w & 1;     // 4 x 2 warp grid, warp tile 32x64
    int bm = blockIdx.y, bn = blockIdx.x;

    const uint16_t* A = (MODE == 0) ? gx_f16 : gctx_f16;
    const uint16_t* Bw = (MODE == 0) ? gwi_f16 : gwo_f16;

    // loaders: 2 thr/row (64B row), 2 16B-groups per thread
    int r = tid >> 1, g0 = (tid & 1) * 2;
    size_t aoff = (size_t)(bm * 128 + r) * HIDDEN;
    size_t boff = (size_t)(bn * 128 + r) * HIDDEN;

    float acc[2][8][4];
#pragma unroll
    for (int i = 0; i < 2; i++)
#pragma unroll
        for (int j = 0; j < 8; j++)
#pragma unroll
            for (int e = 0; e < 4; e++) acc[i][j][e] = 0.f;

#define ISSUE_CHUNK(kc, buf) do {                                               \
        uint32_t dst = sbase + (uint32_t)(buf) * GSTAGE;                         \
        const uint16_t* ap = A  + aoff + (kc) * 32;                              \
        const uint16_t* bp = Bw + boff + (kc) * 32;                              \
        _Pragma("unroll")                                                        \
        for (int i = 0; i < 2; i++) {                                            \
            uint32_t so = swz64((uint32_t)r * 64u + (uint32_t)(g0 + i) * 16u);   \
            cp16(dst + so,          ap + (g0 + i) * 8);                          \
            cp16(dst + 8192u + so,  bp + (g0 + i) * 8);                          \
        }                                                                        \
        cp_commit();                                                             \
    } while (0)

    ISSUE_CHUNK(0, 0);

    const int NK = HIDDEN / 32;   // 16 chunks
    int rb = 0;                   // read buffer = kc % 3
    for (int kc = 0; kc < NK; kc++) {
        if (kc + 1 < NK) {
            int wb = rb + 1; if (wb == 3) wb = 0;
            ISSUE_CHUNK(kc + 1, wb);
            cp_wait<1>();
        } else {
            cp_wait<0>();
        }
        __syncthreads();   // single barrier per chunk (3-buf ring makes tail-write safe)

        uint32_t abase = sbase + (uint32_t)rb * GSTAGE;
        uint32_t bbase = abase + 8192u;
#pragma unroll
        for (int ks = 0; ks < 2; ks++) {
            uint32_t ah[2][4];
#pragma unroll
            for (int mi = 0; mi < 2; mi++) {
                uint32_t off = swz64((uint32_t)(wm * 32 + mi * 16 + (lane & 15)) * 64u
                                     + (uint32_t)(ks * 32 + ((lane & 16) ? 16 : 0)));
                ldsm4(ah[mi][0], ah[mi][1], ah[mi][2], ah[mi][3], abase + off);
            }
#pragma unroll
            for (int np = 0; np < 4; np++) {
                uint32_t boffs = swz64((uint32_t)(wn * 64 + np * 16 + (lane & 7)
                                                  + ((lane & 16) ? 8 : 0)) * 64u
                                       + (uint32_t)(ks * 32 + ((lane & 8) ? 16 : 0)));
                uint32_t b0, b1, b2, b3;
                ldsm4(b0, b1, b2, b3, bbase + boffs);
#pragma unroll
                for (int mi = 0; mi < 2; mi++) {
                    mma_f16(acc[mi][2 * np],     ah[mi], b0, b1);
                    mma_f16(acc[mi][2 * np + 1], ah[mi], b2, b3);
                }
            }
        }
        rb = rb + 1; if (rb == 3) rb = 0;
    }
#undef ISSUE_CHUNK

    // ---- epilogue ----
#pragma unroll
    for (int mi = 0; mi < 2; mi++) {
        int r0 = bm * 128 + wm * 32 + mi * 16 + (lane >> 2);
#pragma unroll
        for (int nj = 0; nj < 8; nj++) {
            int c0 = bn * 128 + wn * 64 + nj * 8 + 2 * (lane & 3);
            float bb0 = __ldg(bias + c0), bb1 = __ldg(bias + c0 + 1);
            float v0 = acc[mi][nj][0] + bb0, v1 = acc[mi][nj][1] + bb1;
            float v2 = acc[mi][nj][2] + bb0, v3 = acc[mi][nj][3] + bb1;
            if (MODE == 0) {
                int which = c0 >> 9, h = (c0 >> 6) & 7, d = c0 & 63;
                uint16_t* dq = (which == 0) ? gq_f16 : (which == 1) ? gk_f16 : gv_f16;
                int b = r0 >> 12;
                size_t base0 = ((size_t)((b * 8 + h) * L_ + (r0 & 4095))) * 64 + d;
                size_t base1 = base0 + 8 * 64;
                *(uint32_t*)(dq + base0) = cvt_f16x2(v0, v1);
                *(uint32_t*)(dq + base1) = cvt_f16x2(v2, v3);
            } else {
                *(float2*)(Cout + (size_t)r0 * HIDDEN + c0) = make_float2(v0, v1);
                *(float2*)(Cout + (size_t)(r0 + 8) * HIDDEN + c0) = make_float2(v2, v3);
            }
        }
    }
}

// ============================================================
// Attention (single-pass fp16): Q 16KB; K/V 3-buffer ring
// (3 x 16KB: K 8KB + V 8KB), depth-1 prefetch, ONE sync per tile.
// Total 64KB. 2 CTAs/SM.
// ============================================================
#define SQ   0u
#define SKV0 16384u
#define ATTN_SMEM 65536

__global__ __launch_bounds__(256, 2) void attn_mma_kernel()
{
    extern __shared__ char smp[];
    const uint32_t sbase = smem_u32(smp);
    int tid = threadIdx.x;
    int w = tid >> 5, lane = tid & 31;

    int bh = blockIdx.x;                            // b*8 + h
    int qt = (int)gridDim.y - 1 - (int)blockIdx.y;  // heavy tiles first
    int nkt = 2 * qt + 2;                           // 64-key tiles

    int ct = tid & 127;
    int rr = ct >> 1, g0 = (ct & 1) * 4;
    const uint16_t* srckv = (tid < 128) ? gk_f16 : gv_f16;
    uint32_t dsel = (tid < 128) ? 0u : 8192u;

#define ISSUE_KV(kt, buf) do {                                                   \
        uint32_t dst = sbase + SKV0 + (uint32_t)(buf) * 16384u + dsel;           \
        const uint16_t* sp = srckv + ((size_t)bh * L_ + (size_t)(kt) * 64 + rr) * 64; \
        _Pragma("unroll")                                                        \
        for (int i = 0; i < 4; i++) {                                            \
            uint32_t so = swz128((uint32_t)rr * 128u + (uint32_t)(g0 + i) * 16u);\
            cp16(dst + so, sp + (g0 + i) * 8);                                   \
        }                                                                        \
        cp_commit();                                                             \
    } while (0)

    // Prologue: Q tile copy + first K/V issue
    {
        const uint4* q4 = (const uint4*)(gq_f16 + ((size_t)bh * L_ + (size_t)qt * 128 + (tid >> 1)) * 64);
        int qg0 = (tid & 1) * 4;
#pragma unroll
        for (int i = 0; i < 4; i++) {
            uint32_t so = swz128((uint32_t)(tid >> 1) * 128u + (uint32_t)(qg0 + i) * 16u);
            *(uint4*)(smp + SQ + so) = q4[qg0 + i];
        }
    }
    ISSUE_KV(0, 0);
    __syncthreads();

    int arow = 16 * w + (lane & 15);
    uint32_t qf[4][4];   // fp16 Q A-fragments, resident whole kernel
    {
#pragma unroll
        for (int ks = 0; ks < 4; ks++) {
            uint32_t off = swz128((uint32_t)arow * 128u
                                  + (uint32_t)(ks * 32 + ((lane & 16) ? 16 : 0)));
            ldsm4(qf[ks][0], qf[ks][1], qf[ks][2], qf[ks][3], sbase + SQ + off);
        }
    }

    float oc[8][4];
#pragma unroll
    for (int n = 0; n < 8; n++)
#pragma unroll
        for (int j = 0; j < 4; j++) oc[n][j] = 0.f;
    float lsum0 = 0.f, lsum1 = 0.f;

    const float Cc = 0.18033688011112042f;  // (1/8) * log2(e)
    int row0 = qt * 128 + 16 * w + (lane >> 2);
    int row1 = row0 + 8;

    int rbuf = 0;   // read buffer = kt % 3
    for (int kt = 0; kt < nkt; ++kt) {
        if (kt + 1 < nkt) {
            int wb = rbuf + 1; if (wb == 3) wb = 0;
            ISSUE_KV(kt + 1, wb);
            cp_wait<1>();
        } else {
            cp_wait<0>();
        }
        __syncthreads();   // single barrier per tile (3-buf ring)

        uint32_t kvb = sbase + SKV0 + (uint32_t)rbuf * 16384u;

        // ---- S = Q K^T : single-pass fp16 ----
        float sc[8][4];
#pragma unroll
        for (int n = 0; n < 8; n++)
#pragma unroll
            for (int j = 0; j < 4; j++) sc[n][j] = 0.f;

#pragma unroll
        for (int ks = 0; ks < 4; ks++) {
#pragma unroll
            for (int npp = 0; npp < 2; npp++) {
                int key0 = (2 * npp) * 16 + (lane & 7) + ((lane & 16) ? 8 : 0);
                uint32_t col = (uint32_t)(ks * 32 + ((lane & 8) ? 16 : 0));
                uint32_t off0 = swz128((uint32_t)key0 * 128u + col);
                uint32_t off1 = swz128((uint32_t)(key0 + 16) * 128u + col);
                uint32_t b00, b01, b02, b03, b10, b11, b12, b13;
                ldsm4(b00, b01, b02, b03, kvb + off0);
                ldsm4(b10, b11, b12, b13, kvb + off1);
                mma_f16(sc[4 * npp + 0], qf[ks], b00, b01);
                mma_f16(sc[4 * npp + 1], qf[ks], b02, b03);
                mma_f16(sc[4 * npp + 2], qf[ks], b10, b11);
                mma_f16(sc[4 * npp + 3], qf[ks], b12, b13);
            }
        }

        // ---- softmax (unnormalized) ----
        bool edge = (kt == 0) || (kt >= 2 * qt);
        int colb = kt * 64 + 2 * (lane & 3);
#pragma unroll
        for (int n = 0; n < 8; n++) {
            float e0 = ex2f(sc[n][0] * Cc);
            float e1 = ex2f(sc[n][1] * Cc);
            float e2 = ex2f(sc[n][2] * Cc);
            float e3 = ex2f(sc[n][3] * Cc);
            if (edge) {
                int c0 = colb + 8 * n, c1 = c0 + 1;
                bool k00 = (c0 <= row0) && (c0 >= PREFIX || row0 < PREFIX);
                bool k01 = (c1 <= row0) && (c1 >= PREFIX || row0 < PREFIX);
                bool k10 = (c0 <= row1) && (c0 >= PREFIX || row1 < PREFIX);
                bool k11 = (c1 <= row1) && (c1 >= PREFIX || row1 < PREFIX);
                e0 = k00 ? e0 : 0.f;
                e1 = k01 ? e1 : 0.f;
                e2 = k10 ? e2 : 0.f;
                e3 = k11 ? e3 : 0.f;
            }
            sc[n][0] = e0; sc[n][1] = e1; sc[n][2] = e2; sc[n][3] = e3;
            lsum0 += e0 + e1;
            lsum1 += e2 + e3;
        }

        // ---- O += P V : single-pass fp16 ----
#pragma unroll
        for (int t = 0; t < 4; t++) {
            uint32_t pf[4];
            pf[0] = cvt_f16x2(sc[2 * t][0],     sc[2 * t][1]);
            pf[1] = cvt_f16x2(sc[2 * t][2],     sc[2 * t][3]);
            pf[2] = cvt_f16x2(sc[2 * t + 1][0], sc[2 * t + 1][1]);
            pf[3] = cvt_f16x2(sc[2 * t + 1][2], sc[2 * t + 1][3]);
            int key = t * 16 + (lane & 7) + ((lane & 8) ? 8 : 0);
#pragma unroll
            for (int dpp = 0; dpp < 2; dpp++) {
                uint32_t col0 = (uint32_t)((2 * dpp) * 32 + ((lane & 16) ? 16 : 0));
                uint32_t off0 = swz128((uint32_t)key * 128u + col0);
                uint32_t off1 = swz128((uint32_t)key * 128u + col0 + 32u);
                uint32_t v00, v01, v02, v03, v10, v11, v12, v13;
                ldsm4t(v00, v01, v02, v03, kvb + 8192u + off0);
                ldsm4t(v10, v11, v12, v13, kvb + 8192u + off1);
                mma_f16(oc[4 * dpp + 0], pf, v00, v01);
                mma_f16(oc[4 * dpp + 1], pf, v02, v03);
                mma_f16(oc[4 * dpp + 2], pf, v10, v11);
                mma_f16(oc[4 * dpp + 3], pf, v12, v13);
            }
        }
        rbuf = rbuf + 1; if (rbuf == 3) rbuf = 0;
    }
#undef ISSUE_KV

    // lane reduction of lsum
    lsum0 += __shfl_xor_sync(0xffffffffu, lsum0, 1);
    lsum0 += __shfl_xor_sync(0xffffffffu, lsum0, 2);
    lsum1 += __shfl_xor_sync(0xffffffffu, lsum1, 1);
    lsum1 += __shfl_xor_sync(0xffffffffu, lsum1, 2);
    float inv0 = 1.f / lsum0, inv1 = 1.f / lsum1;

    // store ctx as fp16 (gemm1 input)
    int b = bh >> 3, h = bh & 7;
    size_t r0base = (size_t)(b * L_ + row0) * HIDDEN + h * 64;
    size_t r1base = (size_t)(b * L_ + row1) * HIDDEN + h * 64;
#pragma unroll
    for (int n = 0; n < 8; n++) {
        int d = 8 * n + 2 * (lane & 3);
        *(uint32_t*)(gctx_f16 + r0base + d) = cvt_f16x2(oc[n][0] * inv0, oc[n][1] * inv0);
        *(uint32_t*)(gctx_f16 + r1base + d) = cvt_f16x2(oc[n][2] * inv1, oc[n][3] * inv1);
    }
}

// ============================================================
extern "C" void kernel_launch(void* const* d_in, const int* in_sizes, int n_in,
                              void* d_out, int out_size)
{
    const float* x     = (const float*)d_in[0];
    const float* w_in  = (const float*)d_in[1];
    const float* b_in  = (const float*)d_in[2];
    const float* w_out = (const float*)d_in[3];
    const float* b_out = (const float*)d_in[4];
    float* out = (float*)d_out;

    conv_x_kernel<<<(M_ROWS * HIDDEN / 4) / 256, 256>>>(x);
    conv_wT_kernel<<<dim3(3 * HIDDEN / 32, HIDDEN / 32), 256>>>(w_in, HIDDEN, 3 * HIDDEN, 0);
    conv_wT_kernel<<<dim3(HIDDEN / 32, HIDDEN / 32), 256>>>(w_out, HIDDEN, HIDDEN, 1);

    cudaFuncSetAttribute(gemm_f16_kernel<0>,
                         cudaFuncAttributeMaxDynamicSharedMemorySize, 3 * GSTAGE);
    gemm_f16_kernel<0><<<dim3(12, 64), 256, 3 * GSTAGE>>>(b_in, nullptr);

    cudaFuncSetAttribute(attn_mma_kernel,
                         cudaFuncAttributeMaxDynamicSharedMemorySize, ATTN_SMEM);
    attn_mma_kernel<<<dim3(16, 32), 256, ATTN_SMEM>>>();

    cudaFuncSetAttribute(gemm_f16_kernel<1>,
                         cudaFuncAttributeMaxDynamicSharedMemorySize, 3 * GSTAGE);
    gemm_f16_kernel<1><<<dim3(4, 64), 256, 3 * GSTAGE>>>(b_out, out);
}

// round 15
// speedup vs baseline: 1.2327x; 1.0360x over previous
#include <cuda_runtime.h>
#include <cstdint>

typedef unsigned long long ull;

#define B_      2
#define L_      4096
#define HIDDEN  512
#define HEADS   8
#define HD      64
#define PREFIX  1
#define M_ROWS  (B_ * L_)        // 8192
#define CC_SCALE 0.18033688011112042f   // (1/8) * log2(e), folded into Q
#define ONESH2  0x3C003C00u             // fp16x2 {1.0, 1.0}

// ---- fp16 storage (allocation-free: __device__ globals) ----
__device__ __align__(16) uint16_t gx_f16[M_ROWS * HIDDEN];
__device__ __align__(16) uint16_t gwi_f16[3 * HIDDEN * HIDDEN];
__device__ __align__(16) uint16_t gwo_f16[HIDDEN * HIDDEN];
__device__ __align__(16) uint16_t gq_f16[M_ROWS * HIDDEN];
__device__ __align__(16) uint16_t gk_f16[M_ROWS * HIDDEN];
__device__ __align__(16) uint16_t gv_f16[M_ROWS * HIDDEN];
__device__ __align__(16) uint16_t gctx_f16[M_ROWS * HIDDEN];

// ============================================================
// helpers
// ============================================================
__device__ __forceinline__ uint32_t smem_u32(const void* p) {
    uint32_t a;
    asm("{ .reg .u64 t; cvta.to.shared.u64 t, %1; cvt.u32.u64 %0, t; }" : "=r"(a) : "l"(p));
    return a;
}
__device__ __forceinline__ uint32_t cvt_f16x2(float lo, float hi) {
    uint32_t r; asm("cvt.rn.f16x2.f32 %0,%1,%2;" : "=r"(r) : "f"(hi), "f"(lo)); return r;
}
__device__ __forceinline__ float ex2f(float x) {
    float r; asm("ex2.approx.f32 %0,%1;" : "=f"(r) : "f"(x)); return r;
}
__device__ __forceinline__ uint32_t swz128(uint32_t o) { return o ^ ((o >> 3) & 0x70u); }
__device__ __forceinline__ uint32_t swz64(uint32_t o)  { return o ^ ((o >> 3) & 0x30u); }

__device__ __forceinline__ void cp16(uint32_t dst, const void* src) {
    asm volatile("cp.async.cg.shared.global [%0], [%1], 16;" :: "r"(dst), "l"(src) : "memory");
}
__device__ __forceinline__ void cp_commit() {
    asm volatile("cp.async.commit_group;" ::: "memory");
}
template <int N> __device__ __forceinline__ void cp_wait() {
    asm volatile("cp.async.wait_group %0;" :: "n"(N) : "memory");
}

__device__ __forceinline__ void ldsm4(uint32_t& r0, uint32_t& r1, uint32_t& r2, uint32_t& r3,
                                      uint32_t addr) {
    asm volatile("ldmatrix.sync.aligned.m8n8.x4.shared.b16 {%0,%1,%2,%3}, [%4];"
                 : "=r"(r0), "=r"(r1), "=r"(r2), "=r"(r3) : "r"(addr));
}
__device__ __forceinline__ void ldsm4t(uint32_t& r0, uint32_t& r1, uint32_t& r2, uint32_t& r3,
                                       uint32_t addr) {
    asm volatile("ldmatrix.sync.aligned.m8n8.x4.trans.shared.b16 {%0,%1,%2,%3}, [%4];"
                 : "=r"(r0), "=r"(r1), "=r"(r2), "=r"(r3) : "r"(addr));
}
__device__ __forceinline__ void mma_f16(float* c, const uint32_t* a, uint32_t b0, uint32_t b1) {
    asm volatile(
        "mma.sync.aligned.m16n8k16.row.col.f32.f16.f16.f32 "
        "{%0,%1,%2,%3},{%4,%5,%6,%7},{%8,%9},{%0,%1,%2,%3};"
        : "+f"(c[0]), "+f"(c[1]), "+f"(c[2]), "+f"(c[3])
        : "r"(a[0]), "r"(a[1]), "r"(a[2]), "r"(a[3]), "r"(b0), "r"(b1));
}

// ============================================================
// conversion kernels: fp32 -> fp16
// ============================================================
__global__ __launch_bounds__(256) void conv_x_kernel(const float* __restrict__ x)
{
    size_t gid = (size_t)blockIdx.x * 256 + threadIdx.x;
    size_t i = gid * 4;
    float4 v = *(const float4*)(x + i);
    uint2 H;
    H.x = cvt_f16x2(v.x, v.y);
    H.y = cvt_f16x2(v.z, v.w);
    *(uint2*)(gx_f16 + i) = H;
}

__global__ __launch_bounds__(256) void conv_wT_kernel(const float* __restrict__ w,
                                                      int K, int N, int which)
{
    __shared__ float t[32][33];
    uint16_t* dst = which ? gwo_f16 : gwi_f16;
    int n0 = blockIdx.x * 32, k0 = blockIdx.y * 32;
    int tx = threadIdx.x & 31, ty = threadIdx.x >> 5;
#pragma unroll
    for (int i = 0; i < 4; i++)
        t[ty + 8 * i][tx] = w[(size_t)(k0 + ty + 8 * i) * N + n0 + tx];
    __syncthreads();
#pragma unroll
    for (int i = 0; i < 4; i++) {
        int nn = ty + 8 * i;
        float v = t[tx][nn];
        uint16_t h;
        asm("cvt.rn.f16.f32 %0,%1;" : "=h"(h) : "f"(v));
        dst[(size_t)(n0 + nn) * K + k0 + tx] = h;
    }
}

// ============================================================
// GEMM single-pass fp16: CTA tile 128x128, 256 thr, warp tile 32x64,
// k-chunk 32, 3-stage ring + depth-1 prefetch, ONE sync per chunk,
// SW64, 2 CTA/SM. Stage (16KB): {A 0, B 8K}.
// MODE 0 epilogue: q scaled by CC_SCALE (softmax fold).
// ============================================================
#define GSTAGE 16384u

template <int MODE>
__global__ __launch_bounds__(256, 2) void gemm_f16_kernel(
    const float* __restrict__ bias, float* __restrict__ Cout)
{
    extern __shared__ char smp[];
    const uint32_t sbase = smem_u32(smp);
    int tid = threadIdx.x;
    int lane = tid & 31, w = tid >> 5;
    int wm = w >> 1, wn = w & 1;     // 4 x 2 warp grid, warp tile 32x64
    int bm = blockIdx.y, bn = blockIdx.x;

    const uint16_t* A = (MODE == 0) ? gx_f16 : gctx_f16;
    const uint16_t* Bw = (MODE == 0) ? gwi_f16 : gwo_f16;

    int r = tid >> 1, g0 = (tid & 1) * 2;
    size_t aoff = (size_t)(bm * 128 + r) * HIDDEN;
    size_t boff = (size_t)(bn * 128 + r) * HIDDEN;

    float acc[2][8][4];
#pragma unroll
    for (int i = 0; i < 2; i++)
#pragma unroll
        for (int j = 0; j < 8; j++)
#pragma unroll
            for (int e = 0; e < 4; e++) acc[i][j][e] = 0.f;

#define ISSUE_CHUNK(kc, buf) do {                                               \
        uint32_t dst = sbase + (uint32_t)(buf) * GSTAGE;                         \
        const uint16_t* ap = A  + aoff + (kc) * 32;                              \
        const uint16_t* bp = Bw + boff + (kc) * 32;                              \
        _Pragma("unroll")                                                        \
        for (int i = 0; i < 2; i++) {                                            \
            uint32_t so = swz64((uint32_t)r * 64u + (uint32_t)(g0 + i) * 16u);   \
            cp16(dst + so,          ap + (g0 + i) * 8);                          \
            cp16(dst + 8192u + so,  bp + (g0 + i) * 8);                          \
        }                                                                        \
        cp_commit();                                                             \
    } while (0)

    ISSUE_CHUNK(0, 0);

    const int NK = HIDDEN / 32;   // 16 chunks
    int rb = 0;                   // read buffer = kc % 3
    for (int kc = 0; kc < NK; kc++) {
        if (kc + 1 < NK) {
            int wb = rb + 1; if (wb == 3) wb = 0;
            ISSUE_CHUNK(kc + 1, wb);
            cp_wait<1>();
        } else {
            cp_wait<0>();
        }
        __syncthreads();   // single barrier per chunk (3-buf ring)

        uint32_t abase = sbase + (uint32_t)rb * GSTAGE;
        uint32_t bbase = abase + 8192u;
#pragma unroll
        for (int ks = 0; ks < 2; ks++) {
            uint32_t ah[2][4];
#pragma unroll
            for (int mi = 0; mi < 2; mi++) {
                uint32_t off = swz64((uint32_t)(wm * 32 + mi * 16 + (lane & 15)) * 64u
                                     + (uint32_t)(ks * 32 + ((lane & 16) ? 16 : 0)));
                ldsm4(ah[mi][0], ah[mi][1], ah[mi][2], ah[mi][3], abase + off);
            }
#pragma unroll
            for (int np = 0; np < 4; np++) {
                uint32_t boffs = swz64((uint32_t)(wn * 64 + np * 16 + (lane & 7)
                                                  + ((lane & 16) ? 8 : 0)) * 64u
                                       + (uint32_t)(ks * 32 + ((lane & 8) ? 16 : 0)));
                uint32_t b0, b1, b2, b3;
                ldsm4(b0, b1, b2, b3, bbase + boffs);
#pragma unroll
                for (int mi = 0; mi < 2; mi++) {
                    mma_f16(acc[mi][2 * np],     ah[mi], b0, b1);
                    mma_f16(acc[mi][2 * np + 1], ah[mi], b2, b3);
                }
            }
        }
        rb = rb + 1; if (rb == 3) rb = 0;
    }
#undef ISSUE_CHUNK

    // ---- epilogue ----
#pragma unroll
    for (int mi = 0; mi < 2; mi++) {
        int r0 = bm * 128 + wm * 32 + mi * 16 + (lane >> 2);
#pragma unroll
        for (int nj = 0; nj < 8; nj++) {
            int c0 = bn * 128 + wn * 64 + nj * 8 + 2 * (lane & 3);
            float bb0 = __ldg(bias + c0), bb1 = __ldg(bias + c0 + 1);
            float v0 = acc[mi][nj][0] + bb0, v1 = acc[mi][nj][1] + bb1;
            float v2 = acc[mi][nj][2] + bb0, v3 = acc[mi][nj][3] + bb1;
            if (MODE == 0) {
                int which = c0 >> 9, h = (c0 >> 6) & 7, d = c0 & 63;
                uint16_t* dq = (which == 0) ? gq_f16 : (which == 1) ? gk_f16 : gv_f16;
                if (which == 0) {   // fold softmax scale*log2e into Q
                    v0 *= CC_SCALE; v1 *= CC_SCALE; v2 *= CC_SCALE; v3 *= CC_SCALE;
                }
                int b = r0 >> 12;
                size_t base0 = ((size_t)((b * 8 + h) * L_ + (r0 & 4095))) * 64 + d;
                size_t base1 = base0 + 8 * 64;
                *(uint32_t*)(dq + base0) = cvt_f16x2(v0, v1);
                *(uint32_t*)(dq + base1) = cvt_f16x2(v2, v3);
            } else {
                *(float2*)(Cout + (size_t)r0 * HIDDEN + c0) = make_float2(v0, v1);
                *(float2*)(Cout + (size_t)(r0 + 8) * HIDDEN + c0) = make_float2(v2, v3);
            }
        }
    }
}

// ============================================================
// Attention (single-pass fp16, Q pre-scaled): Q 16KB; K/V 3-buffer
// ring (3 x 16KB), depth-1 prefetch, ONE sync per tile. 64KB, 2 CTA/SM.
// lsum via ones-column MMA (no scalar adds, no shuffles).
// ============================================================
#define SQ   0u
#define SKV0 16384u
#define ATTN_SMEM 65536

__global__ __launch_bounds__(256, 2) void attn_mma_kernel()
{
    extern __shared__ char smp[];
    const uint32_t sbase = smem_u32(smp);
    int tid = threadIdx.x;
    int w = tid >> 5, lane = tid & 31;

    int bh = blockIdx.x;                            // b*8 + h
    int qt = (int)gridDim.y - 1 - (int)blockIdx.y;  // heavy tiles first
    int nkt = 2 * qt + 2;                           // 64-key tiles

    int ct = tid & 127;
    int rr = ct >> 1, g0 = (ct & 1) * 4;
    const uint16_t* srckv = (tid < 128) ? gk_f16 : gv_f16;
    uint32_t dsel = (tid < 128) ? 0u : 8192u;

#define ISSUE_KV(kt, buf) do {                                                   \
        uint32_t dst = sbase + SKV0 + (uint32_t)(buf) * 16384u + dsel;           \
        const uint16_t* sp = srckv + ((size_t)bh * L_ + (size_t)(kt) * 64 + rr) * 64; \
        _Pragma("unroll")                                                        \
        for (int i = 0; i < 4; i++) {                                            \
            uint32_t so = swz128((uint32_t)rr * 128u + (uint32_t)(g0 + i) * 16u);\
            cp16(dst + so, sp + (g0 + i) * 8);                                   \
        }                                                                        \
        cp_commit();                                                             \
    } while (0)

    // Prologue: Q tile copy + first K/V issue
    {
        const uint4* q4 = (const uint4*)(gq_f16 + ((size_t)bh * L_ + (size_t)qt * 128 + (tid >> 1)) * 64);
        int qg0 = (tid & 1) * 4;
#pragma unroll
        for (int i = 0; i < 4; i++) {
            uint32_t so = swz128((uint32_t)(tid >> 1) * 128u + (uint32_t)(qg0 + i) * 16u);
            *(uint4*)(smp + SQ + so) = q4[qg0 + i];
        }
    }
    ISSUE_KV(0, 0);
    __syncthreads();

    int arow = 16 * w + (lane & 15);
    uint32_t qf[4][4];   // fp16 Q A-fragments (pre-scaled), resident whole kernel
    {
#pragma unroll
        for (int ks = 0; ks < 4; ks++) {
            uint32_t off = swz128((uint32_t)arow * 128u
                                  + (uint32_t)(ks * 32 + ((lane & 16) ? 16 : 0)));
            ldsm4(qf[ks][0], qf[ks][1], qf[ks][2], qf[ks][3], sbase + SQ + off);
        }
    }

    float oc[8][4];
#pragma unroll
    for (int n = 0; n < 8; n++)
#pragma unroll
        for (int j = 0; j < 4; j++) oc[n][j] = 0.f;
    float lsC[4] = {0.f, 0.f, 0.f, 0.f};   // row sums via ones-MMA

    int row0 = qt * 128 + 16 * w + (lane >> 2);
    int row1 = row0 + 8;

    int rbuf = 0;   // read buffer = kt % 3
    for (int kt = 0; kt < nkt; ++kt) {
        if (kt + 1 < nkt) {
            int wb = rbuf + 1; if (wb == 3) wb = 0;
            ISSUE_KV(kt + 1, wb);
            cp_wait<1>();
        } else {
            cp_wait<0>();
        }
        __syncthreads();   // single barrier per tile (3-buf ring)

        uint32_t kvb = sbase + SKV0 + (uint32_t)rbuf * 16384u;

        // ---- S = Q K^T (pre-scaled Q -> S already in log2 domain) ----
        float sc[8][4];
#pragma unroll
        for (int n = 0; n < 8; n++)
#pragma unroll
            for (int j = 0; j < 4; j++) sc[n][j] = 0.f;

#pragma unroll
        for (int ks = 0; ks < 4; ks++) {
#pragma unroll
            for (int npp = 0; npp < 2; npp++) {
                int key0 = (2 * npp) * 16 + (lane & 7) + ((lane & 16) ? 8 : 0);
                uint32_t col = (uint32_t)(ks * 32 + ((lane & 8) ? 16 : 0));
                uint32_t off0 = swz128((uint32_t)key0 * 128u + col);
                uint32_t off1 = swz128((uint32_t)(key0 + 16) * 128u + col);
                uint32_t b00, b01, b02, b03, b10, b11, b12, b13;
                ldsm4(b00, b01, b02, b03, kvb + off0);
                ldsm4(b10, b11, b12, b13, kvb + off1);
                mma_f16(sc[4 * npp + 0], qf[ks], b00, b01);
                mma_f16(sc[4 * npp + 1], qf[ks], b02, b03);
                mma_f16(sc[4 * npp + 2], qf[ks], b10, b11);
                mma_f16(sc[4 * npp + 3], qf[ks], b12, b13);
            }
        }

        // ---- masking: only on edge tiles, sentinel -100 -> exp2 ~ 0 ----
        if ((kt == 0) || (kt >= 2 * qt)) {
            int colb = kt * 64 + 2 * (lane & 3);
#pragma unroll
            for (int n = 0; n < 8; n++) {
                int c0 = colb + 8 * n, c1 = c0 + 1;
                if (!((c0 <= row0) && (c0 >= PREFIX || row0 < PREFIX))) sc[n][0] = -100.f;
                if (!((c1 <= row0) && (c1 >= PREFIX || row0 < PREFIX))) sc[n][1] = -100.f;
                if (!((c0 <= row1) && (c0 >= PREFIX || row1 < PREFIX))) sc[n][2] = -100.f;
                if (!((c1 <= row1) && (c1 >= PREFIX || row1 < PREFIX))) sc[n][3] = -100.f;
            }
        }

        // ---- exp2 + P pack + lsum(ones-MMA) + PV ----
#pragma unroll
        for (int t = 0; t < 4; t++) {
            uint32_t pf[4];
            pf[0] = cvt_f16x2(ex2f(sc[2 * t][0]),     ex2f(sc[2 * t][1]));
            pf[1] = cvt_f16x2(ex2f(sc[2 * t][2]),     ex2f(sc[2 * t][3]));
            pf[2] = cvt_f16x2(ex2f(sc[2 * t + 1][0]), ex2f(sc[2 * t + 1][1]));
            pf[3] = cvt_f16x2(ex2f(sc[2 * t + 1][2]), ex2f(sc[2 * t + 1][3]));
            mma_f16(lsC, pf, ONESH2, ONESH2);   // row sums accumulate in fp32
            int key = t * 16 + (lane & 7) + ((lane & 8) ? 8 : 0);
#pragma unroll
            for (int dpp = 0; dpp < 2; dpp++) {
                uint32_t col0 = (uint32_t)((2 * dpp) * 32 + ((lane & 16) ? 16 : 0));
                uint32_t off0 = swz128((uint32_t)key * 128u + col0);
                uint32_t off1 = swz128((uint32_t)key * 128u + col0 + 32u);
                uint32_t v00, v01, v02, v03, v10, v11, v12, v13;
                ldsm4t(v00, v01, v02, v03, kvb + 8192u + off0);
                ldsm4t(v10, v11, v12, v13, kvb + 8192u + off1);
                mma_f16(oc[4 * dpp + 0], pf, v00, v01);
                mma_f16(oc[4 * dpp + 1], pf, v02, v03);
                mma_f16(oc[4 * dpp + 2], pf, v10, v11);
                mma_f16(oc[4 * dpp + 3], pf, v12, v13);
            }
        }
        rbuf = rbuf + 1; if (rbuf == 3) rbuf = 0;
    }
#undef ISSUE_KV

    // lsC[0] = lsum(row0), lsC[2] = lsum(row1) — already complete per lane
    float inv0 = 1.f / lsC[0], inv1 = 1.f / lsC[2];

    // store ctx as fp16 (gemm1 input)
    int b = bh >> 3, h = bh & 7;
    size_t r0base = (size_t)(b * L_ + row0) * HIDDEN + h * 64;
    size_t r1base = (size_t)(b * L_ + row1) * HIDDEN + h * 64;
#pragma unroll
    for (int n = 0; n < 8; n++) {
        int d = 8 * n + 2 * (lane & 3);
        *(uint32_t*)(gctx_f16 + r0base + d) = cvt_f16x2(oc[n][0] * inv0, oc[n][1] * inv0);
        *(uint32_t*)(gctx_f16 + r1base + d) = cvt_f16x2(oc[n][2] * inv1, oc[n][3] * inv1);
    }
}

// ============================================================
extern "C" void kernel_launch(void* const* d_in, const int* in_sizes, int n_in,
                              void* d_out, int out_size)
{
    const float* x     = (const float*)d_in[0];
    const float* w_in  = (const float*)d_in[1];
    const float* b_in  = (const float*)d_in[2];
    const float* w_out = (const float*)d_in[3];
    const float* b_out = (const float*)d_in[4];
    float* out = (float*)d_out;

    conv_x_kernel<<<(M_ROWS * HIDDEN / 4) / 256, 256>>>(x);
    conv_wT_kernel<<<dim3(3 * HIDDEN / 32, HIDDEN / 32), 256>>>(w_in, HIDDEN, 3 * HIDDEN, 0);
    conv_wT_kernel<<<dim3(HIDDEN / 32, HIDDEN / 32), 256>>>(w_out, HIDDEN, HIDDEN, 1);

    cudaFuncSetAttribute(gemm_f16_kernel<0>,
                         cudaFuncAttributeMaxDynamicSharedMemorySize, 3 * GSTAGE);
    gemm_f16_kernel<0><<<dim3(12, 64), 256, 3 * GSTAGE>>>(b_in, nullptr);

    cudaFuncSetAttribute(attn_mma_kernel,
                         cudaFuncAttributeMaxDynamicSharedMemorySize, ATTN_SMEM);
    attn_mma_kernel<<<dim3(16, 32), 256, ATTN_SMEM>>>();

    cudaFuncSetAttribute(gemm_f16_kernel<1>,
                         cudaFuncAttributeMaxDynamicSharedMemorySize, 3 * GSTAGE);
    gemm_f16_kernel<1><<<dim3(4, 64), 256, 3 * GSTAGE>>>(b_out, out);
}